// round 15
// baseline (speedup 1.0000x reference)
#include <cuda_runtime.h>
#include <cuda_bf16.h>

// Problem constants (fixed by reference setup_inputs)
#define HH   1024
#define WW   1024
#define NC   8
#define NCOL (WW * NC)      // 8192 flat columns in [y][x][c] layout
#define NSEG 32
#define SEGH (HH / NSEG)    // 32
#define NPOOL 7

// Scratch: SAT in channel-last layout [y][x][c], fp32. 32 MB (fits L2).
__device__ float g_sat[(size_t)HH * NCOL];
// Decoupled-lookback links per (seg, flat col).
__device__ unsigned long long g_link[NSEG * NCOL];   // 2 MB

// ---------------------------------------------------------------------------
// Pass 1: inclusive row scan (along x), 4 elements per thread (float4),
// register-sequential prefix + warp scan of totals + 8-warp block combine.
// Transpose to channel-last layout via padded smem for coalesced stores.
// One block (256 threads) per row y. __launch_bounds__(256,6) trades a few
// register spills for 6 blocks/SM (was 4) — kernel is latency-bound.
// Also resets lookback links (256/row).
// ---------------------------------------------------------------------------
__global__ void __launch_bounds__(256, 6) rowscan_kernel(const float* __restrict__ in) {
    __shared__ float wsum[NC][8];
    __shared__ float sbuf[256 * 33];      // padded transpose buffer (33 KB)

    const int y    = blockIdx.x;
    const int t    = threadIdx.x;
    const int lane = t & 31;
    const int wid  = t >> 5;

    // Reset lookback links: NSEG*NCOL = 262144 entries / 1024 rows = 256 each.
    g_link[(size_t)y * 256 + t] = 0ull;

    // Load 4 consecutive x per channel; sequential in-register prefix.
    float4 v[NC];
    float  tot[NC], excl[NC];
    #pragma unroll
    for (int c = 0; c < NC; ++c) {
        v[c] = ((const float4*)(in + (size_t)c * (HH * WW) + (size_t)y * WW))[t];
        v[c].y += v[c].x;
        v[c].z += v[c].y;
        v[c].w += v[c].z;
        tot[c] = v[c].w;
    }

    // Warp inclusive scan of per-thread totals; derive exclusive offset.
    #pragma unroll
    for (int c = 0; c < NC; ++c) {
        float s = tot[c];
        #pragma unroll
        for (int d = 1; d < 32; d <<= 1) {
            float nb = __shfl_up_sync(0xffffffffu, s, d);
            if (lane >= d) s += nb;
        }
        excl[c] = s - tot[c];
        if (lane == 31) wsum[c][wid] = s;
    }
    __syncthreads();

    // Warp 0 scans the 8 warp totals per channel (width-8 groups).
    if (wid == 0) {
        #pragma unroll
        for (int c = 0; c < NC; ++c) {
            float w = (lane < 8) ? wsum[c][lane] : 0.f;
            #pragma unroll
            for (int d = 1; d < 8; d <<= 1) {
                float nb = __shfl_up_sync(0xffffffffu, w, d);
                if ((lane & 7) >= d) w += nb;
            }
            if (lane < 8) wsum[c][lane] = w;
        }
    }
    __syncthreads();

    // Final values -> padded smem in [x][c] order: idx = 33*t + 8*i + c.
    #pragma unroll
    for (int c = 0; c < NC; ++c) {
        float off = excl[c] + (wid ? wsum[c][wid - 1] : 0.f);
        sbuf[33 * t + c]      = v[c].x + off;
        sbuf[33 * t + 8 + c]  = v[c].y + off;
        sbuf[33 * t + 16 + c] = v[c].z + off;
        sbuf[33 * t + 24 + c] = v[c].w + off;
    }
    __syncthreads();

    // Coalesced float4 stores: output float index o -> smem idx = o + o/32.
    float4* out4 = (float4*)(g_sat + (size_t)y * NCOL);
    #pragma unroll
    for (int j = 0; j < 8; ++j) {
        const int o   = (j * 256 + t) * 4;
        const int idx = o + (o >> 5);
        out4[j * 256 + t] = make_float4(sbuf[idx], sbuf[idx + 1],
                                        sbuf[idx + 2], sbuf[idx + 3]);
    }
}

// ---------------------------------------------------------------------------
// Pass 2: single-pass column cumsum, decoupled lookback with early aggregate
// publish. Block = 1 segment (32 rows) x 256 columns; seg ascends with
// blockIdx (deps point to lower bids -> no deadlock).
// ---------------------------------------------------------------------------
__global__ void __launch_bounds__(256) colscan_kernel() {
    const int tid   = threadIdx.x;
    const int seg   = blockIdx.x >> 5;       // NCOL/256 = 32 chunks per seg
    const int chunk = blockIdx.x & 31;
    const int f     = chunk * 256 + tid;

    float* base = g_sat + (size_t)seg * SEGH * NCOL + f;

    // Local inclusive prefix over the 32 segment rows (reg-resident).
    float pref[SEGH];
    float s = 0.f;
    #pragma unroll
    for (int k = 0; k < SEGH; ++k) {
        s += __ldcg(base + (size_t)k * NCOL);
        pref[k] = s;
    }

    // Publish local aggregate immediately (flag = 1).
    if (seg < NSEG - 1) {
        unsigned long long agg =
            ((unsigned long long)__float_as_uint(s) << 32) | 1ull;
        atomicExch(&g_link[(size_t)seg * NCOL + f], agg);
    }

    // Lookback: walk predecessors, summing aggregates, stop at an inclusive.
    float off = 0.f;
    for (int i = seg - 1; i >= 0; --i) {
        unsigned long long u;
        do {
            u = atomicAdd(&g_link[(size_t)i * NCOL + f], 0ull);
        } while (!(u & 1ull));
        off += __uint_as_float((unsigned)(u >> 32));
        if (u & 2ull) break;       // that value was inclusive -> done
    }

    // Publish inclusive prefix (flag = 3).
    if (seg < NSEG - 1) {
        unsigned long long inc =
            ((unsigned long long)__float_as_uint(off + s) << 32) | 3ull;
        atomicExch(&g_link[(size_t)seg * NCOL + f], inc);
    }

    // Finalize in place.
    #pragma unroll
    for (int k = 0; k < SEGH; ++k)
        __stcg(base + (size_t)k * NCOL, pref[k] + off);
}

// ---------------------------------------------------------------------------
// Pass 3: adaptive 7x7 ROI pooling. One warp per ROI. Warp-cooperative
// geometry prologue (lane slots: 0-6 yhi, 7-13 ylo, 16-22 xhi, 23-29 xlo as
// SAT byte offsets, OOB = -2^30; weights: 0-6 = 1/dy, 8-14 = 1/dx).
// Task loop: 392 tasks = 49 bins x 4 corners x 2 halves; with e = 32k + l,
// the corner bits ((e>>1)&1, (e>>2)&1), the sign, and the channel half are
// LANE-CONSTANT -> hoisted out of the loop (sign applied once pre-reduction,
// half folded into the base pointer). Per iter: div-by-7 + 3 shuffles +
// predicated float4 load + 4 FFMA. Even/odd lanes fetch the two 16B halves
// of the same 32B corner sector (halves L1 wavefronts).
// ---------------------------------------------------------------------------
__global__ void __launch_bounds__(256) pool_kernel(const int* __restrict__ rois,
                                                   float* __restrict__ out, int n) {
    const int warp = (blockIdx.x * blockDim.x + threadIdx.x) >> 5;
    const int l    = threadIdx.x & 31;
    if (warp >= n) return;

    // Broadcast ROI load (all lanes same address -> 1 line).
    const int4 R = ((const int4*)rois)[warp];
    const int ymin = R.x >> 5;            // // FEAT_STRIDE (=32)
    const int xmin = R.y >> 5;
    const int leny = (R.z >> 5) + 1 - ymin;
    const int lenx = (R.w >> 5) + 1 - xmin;

    // ---- per-lane geometry slot (coords) ----
    const bool ySide = (l < 14);
    const int  q     = ySide ? l : (l - 16);       // 0..13 (garbage 14,15,30,31)
    const int  qi    = (q >= 7) ? (q - 7) : q;     // bin index 0..6
    const bool isLo  = (q >= 7);
    const int  len   = ySide ? leny : lenx;
    const int  mn    = ySide ? ymin : xmin;
    const int  blo   = mn + (qi * len) / NPOOL;
    const int  bhi   = mn + ((qi + 1) * len + NPOOL - 1) / NPOOL;
    const int  edge  = isLo ? blo : bhi;
    const int  scale = ySide ? 32768 : 32;         // SAT byte strides: row, x
    const int  vc    = (edge == 0) ? (-(1 << 30)) : (edge - 1) * scale;

    // ---- per-lane weight slot ----
    const bool wy   = (l < 8);
    const int  wi   = wy ? l : (l - 8);            // 0..7 (7 unused)
    const int  wlen = wy ? leny : lenx;
    const int  wmn  = wy ? ymin : xmin;
    const int  wlo  = wmn + (wi * wlen) / NPOOL;
    const int  whi  = wmn + ((wi + 1) * wlen + NPOOL - 1) / NPOOL;
    const float vw  = 1.f / (float)(whi - wlo);

    // ---- lane-constant task attributes (e = 32k + l) ----
    const int  ybase = ((l >> 1) & 1) * 7;         // ylo slots start at 7
    const int  xbase = 16 + ((l >> 2) & 1) * 7;    // xlo slots start at 23
    const int  b0    = l >> 3;                     // bin = 4k + b0
    const bool neg   = ((l >> 1) ^ (l >> 2)) & 1;  // corner sign (lane-const)
    const char* satb = (const char*)g_sat + (l & 1) * 16;  // channel half

    float4 acc = make_float4(0.f, 0.f, 0.f, 0.f);

    #pragma unroll
    for (int k = 0; k < 13; ++k) {
        const int b = 4 * k + b0;                  // bin 0..51 (>=49 = padding)
        const int i = b / 7;
        const int j = b - i * 7;

        const int yoff = __shfl_sync(0xffffffffu, vc, i + ybase);
        const int xoff = __shfl_sync(0xffffffffu, vc, j + xbase);
        const float w  = __shfl_sync(0xffffffffu, vw, i)
                       * __shfl_sync(0xffffffffu, vw, 8 + j);

        int off = yoff + xoff;
        if (b >= 49) off = -1;                     // padding tasks

        if (off >= 0) {
            const float4 v = *(const float4*)(satb + (size_t)off);
            acc.x += w * v.x; acc.y += w * v.y;
            acc.z += w * v.z; acc.w += w * v.w;
        }
    }

    // Apply lane-constant corner sign, then reduce across lanes of same
    // parity (strides 2..16 preserve parity = channel half).
    if (neg) { acc.x = -acc.x; acc.y = -acc.y; acc.z = -acc.z; acc.w = -acc.w; }
    #pragma unroll
    for (int d = 2; d <= 16; d <<= 1) {
        acc.x += __shfl_xor_sync(0xffffffffu, acc.x, d);
        acc.y += __shfl_xor_sync(0xffffffffu, acc.y, d);
        acc.z += __shfl_xor_sync(0xffffffffu, acc.z, d);
        acc.w += __shfl_xor_sync(0xffffffffu, acc.w, d);
    }

    if (l < 2) {
        const float s = 1.f / 49.f;
        ((float4*)(out + (size_t)warp * 8))[l] =
            make_float4(acc.x * s, acc.y * s, acc.z * s, acc.w * s);
    }
}

// ---------------------------------------------------------------------------
extern "C" void kernel_launch(void* const* d_in, const int* in_sizes, int n_in,
                              void* d_out, int out_size) {
    const float* conv = (const float*)d_in[0];   // [8,1024,1024] fp32
    const int*   rois = (const int*)d_in[1];     // [n,4] int32
    float*       out  = (float*)d_out;           // [n,8] fp32
    const int n = in_sizes[1] / 4;

    rowscan_kernel<<<HH, 256>>>(conv);
    colscan_kernel<<<NSEG * (NCOL / 256), 256>>>();
    pool_kernel   <<<(n + 7) / 8, 256>>>(rois, out, n);
}

// round 16
// speedup vs baseline: 1.0693x; 1.0693x over previous
#include <cuda_runtime.h>
#include <cuda_bf16.h>

// Problem constants (fixed by reference setup_inputs)
#define HH   1024
#define WW   1024
#define NC   8
#define NCOL (WW * NC)      // 8192 flat columns in [y][x][c] layout
#define NSEG 32
#define SEGH (HH / NSEG)    // 32
#define NPOOL 7

// Scratch: SAT in channel-last layout [y][x][c], fp32. 32 MB (fits L2).
__device__ float g_sat[(size_t)HH * NCOL];
// Decoupled-lookback links per (seg, flat col).
__device__ unsigned long long g_link[NSEG * NCOL];   // 2 MB

// ---------------------------------------------------------------------------
// Pass 1: inclusive row scan (along x), 4 elements per thread (float4),
// register-sequential prefix + warp scan of totals + 8-warp block combine.
// Transpose to channel-last layout via padded smem for coalesced stores.
// One block (256 threads) per row y. Plain launch bounds: 63 regs / 4
// blocks/SM measured FASTER than forced 6 blocks/SM (spills dominate).
// Also resets lookback links (256/row).
// ---------------------------------------------------------------------------
__global__ void __launch_bounds__(256) rowscan_kernel(const float* __restrict__ in) {
    __shared__ float wsum[NC][8];
    __shared__ float sbuf[256 * 33];      // padded transpose buffer (33 KB)

    const int y    = blockIdx.x;
    const int t    = threadIdx.x;
    const int lane = t & 31;
    const int wid  = t >> 5;

    // Reset lookback links: NSEG*NCOL = 262144 entries / 1024 rows = 256 each.
    g_link[(size_t)y * 256 + t] = 0ull;

    // Load 4 consecutive x per channel; sequential in-register prefix.
    float4 v[NC];
    float  tot[NC], excl[NC];
    #pragma unroll
    for (int c = 0; c < NC; ++c) {
        v[c] = ((const float4*)(in + (size_t)c * (HH * WW) + (size_t)y * WW))[t];
        v[c].y += v[c].x;
        v[c].z += v[c].y;
        v[c].w += v[c].z;
        tot[c] = v[c].w;
    }

    // Warp inclusive scan of per-thread totals; derive exclusive offset.
    #pragma unroll
    for (int c = 0; c < NC; ++c) {
        float s = tot[c];
        #pragma unroll
        for (int d = 1; d < 32; d <<= 1) {
            float nb = __shfl_up_sync(0xffffffffu, s, d);
            if (lane >= d) s += nb;
        }
        excl[c] = s - tot[c];
        if (lane == 31) wsum[c][wid] = s;
    }
    __syncthreads();

    // Warp 0 scans the 8 warp totals per channel (width-8 groups).
    if (wid == 0) {
        #pragma unroll
        for (int c = 0; c < NC; ++c) {
            float w = (lane < 8) ? wsum[c][lane] : 0.f;
            #pragma unroll
            for (int d = 1; d < 8; d <<= 1) {
                float nb = __shfl_up_sync(0xffffffffu, w, d);
                if ((lane & 7) >= d) w += nb;
            }
            if (lane < 8) wsum[c][lane] = w;
        }
    }
    __syncthreads();

    // Final values -> padded smem in [x][c] order: idx = 33*t + 8*i + c.
    #pragma unroll
    for (int c = 0; c < NC; ++c) {
        float off = excl[c] + (wid ? wsum[c][wid - 1] : 0.f);
        sbuf[33 * t + c]      = v[c].x + off;
        sbuf[33 * t + 8 + c]  = v[c].y + off;
        sbuf[33 * t + 16 + c] = v[c].z + off;
        sbuf[33 * t + 24 + c] = v[c].w + off;
    }
    __syncthreads();

    // Coalesced float4 stores: output float index o -> smem idx = o + o/32.
    float4* out4 = (float4*)(g_sat + (size_t)y * NCOL);
    #pragma unroll
    for (int j = 0; j < 8; ++j) {
        const int o   = (j * 256 + t) * 4;
        const int idx = o + (o >> 5);
        out4[j * 256 + t] = make_float4(sbuf[idx], sbuf[idx + 1],
                                        sbuf[idx + 2], sbuf[idx + 3]);
    }
}

// ---------------------------------------------------------------------------
// Pass 2: single-pass column cumsum, decoupled lookback with early aggregate
// publish. Block = 1 segment (32 rows) x 256 columns; seg ascends with
// blockIdx (deps point to lower bids -> no deadlock).
// ---------------------------------------------------------------------------
__global__ void __launch_bounds__(256) colscan_kernel() {
    const int tid   = threadIdx.x;
    const int seg   = blockIdx.x >> 5;       // NCOL/256 = 32 chunks per seg
    const int chunk = blockIdx.x & 31;
    const int f     = chunk * 256 + tid;

    float* base = g_sat + (size_t)seg * SEGH * NCOL + f;

    // Local inclusive prefix over the 32 segment rows (reg-resident).
    float pref[SEGH];
    float s = 0.f;
    #pragma unroll
    for (int k = 0; k < SEGH; ++k) {
        s += __ldcg(base + (size_t)k * NCOL);
        pref[k] = s;
    }

    // Publish local aggregate immediately (flag = 1).
    if (seg < NSEG - 1) {
        unsigned long long agg =
            ((unsigned long long)__float_as_uint(s) << 32) | 1ull;
        atomicExch(&g_link[(size_t)seg * NCOL + f], agg);
    }

    // Lookback: walk predecessors, summing aggregates, stop at an inclusive.
    float off = 0.f;
    for (int i = seg - 1; i >= 0; --i) {
        unsigned long long u;
        do {
            u = atomicAdd(&g_link[(size_t)i * NCOL + f], 0ull);
        } while (!(u & 1ull));
        off += __uint_as_float((unsigned)(u >> 32));
        if (u & 2ull) break;       // that value was inclusive -> done
    }

    // Publish inclusive prefix (flag = 3).
    if (seg < NSEG - 1) {
        unsigned long long inc =
            ((unsigned long long)__float_as_uint(off + s) << 32) | 3ull;
        atomicExch(&g_link[(size_t)seg * NCOL + f], inc);
    }

    // Finalize in place.
    #pragma unroll
    for (int k = 0; k < SEGH; ++k)
        __stcg(base + (size_t)k * NCOL, pref[k] + off);
}

// ---------------------------------------------------------------------------
// Pass 3: adaptive 7x7 ROI pooling. One warp per ROI. Warp-cooperative
// geometry prologue (lane slots: 0-6 yhi, 7-13 ylo, 16-22 xhi, 23-29 xlo as
// SAT byte offsets, OOB = -2^30; weights: 0-6 = 1/dy, 8-14 = 1/dx).
// Task loop: 392 tasks = 49 bins x 4 corners x 2 halves; with e = 32k + l,
// the corner bits, sign, and channel half are LANE-CONSTANT -> hoisted
// (sign applied once pre-reduction, half folded into base pointer).
// Per iter: div-by-7 + 3 shuffles + predicated float4 load + 4 FFMA.
// Even/odd lanes fetch the two 16B halves of the same 32B corner sector.
// [Measured ~10.9 us]
// ---------------------------------------------------------------------------
__global__ void __launch_bounds__(256) pool_kernel(const int* __restrict__ rois,
                                                   float* __restrict__ out, int n) {
    const int warp = (blockIdx.x * blockDim.x + threadIdx.x) >> 5;
    const int l    = threadIdx.x & 31;
    if (warp >= n) return;

    // Broadcast ROI load (all lanes same address -> 1 line).
    const int4 R = ((const int4*)rois)[warp];
    const int ymin = R.x >> 5;            // // FEAT_STRIDE (=32)
    const int xmin = R.y >> 5;
    const int leny = (R.z >> 5) + 1 - ymin;
    const int lenx = (R.w >> 5) + 1 - xmin;

    // ---- per-lane geometry slot (coords) ----
    const bool ySide = (l < 14);
    const int  q     = ySide ? l : (l - 16);       // 0..13 (garbage 14,15,30,31)
    const int  qi    = (q >= 7) ? (q - 7) : q;     // bin index 0..6
    const bool isLo  = (q >= 7);
    const int  len   = ySide ? leny : lenx;
    const int  mn    = ySide ? ymin : xmin;
    const int  blo   = mn + (qi * len) / NPOOL;
    const int  bhi   = mn + ((qi + 1) * len + NPOOL - 1) / NPOOL;
    const int  edge  = isLo ? blo : bhi;
    const int  scale = ySide ? 32768 : 32;         // SAT byte strides: row, x
    const int  vc    = (edge == 0) ? (-(1 << 30)) : (edge - 1) * scale;

    // ---- per-lane weight slot ----
    const bool wy   = (l < 8);
    const int  wi   = wy ? l : (l - 8);            // 0..7 (7 unused)
    const int  wlen = wy ? leny : lenx;
    const int  wmn  = wy ? ymin : xmin;
    const int  wlo  = wmn + (wi * wlen) / NPOOL;
    const int  whi  = wmn + ((wi + 1) * wlen + NPOOL - 1) / NPOOL;
    const float vw  = 1.f / (float)(whi - wlo);

    // ---- lane-constant task attributes (e = 32k + l) ----
    const int  ybase = ((l >> 1) & 1) * 7;         // ylo slots start at 7
    const int  xbase = 16 + ((l >> 2) & 1) * 7;    // xlo slots start at 23
    const int  b0    = l >> 3;                     // bin = 4k + b0
    const bool neg   = ((l >> 1) ^ (l >> 2)) & 1;  // corner sign (lane-const)
    const char* satb = (const char*)g_sat + (l & 1) * 16;  // channel half

    float4 acc = make_float4(0.f, 0.f, 0.f, 0.f);

    #pragma unroll
    for (int k = 0; k < 13; ++k) {
        const int b = 4 * k + b0;                  // bin 0..51 (>=49 = padding)
        const int i = b / 7;
        const int j = b - i * 7;

        const int yoff = __shfl_sync(0xffffffffu, vc, i + ybase);
        const int xoff = __shfl_sync(0xffffffffu, vc, j + xbase);
        const float w  = __shfl_sync(0xffffffffu, vw, i)
                       * __shfl_sync(0xffffffffu, vw, 8 + j);

        int off = yoff + xoff;
        if (b >= 49) off = -1;                     // padding tasks

        if (off >= 0) {
            const float4 v = *(const float4*)(satb + (size_t)off);
            acc.x += w * v.x; acc.y += w * v.y;
            acc.z += w * v.z; acc.w += w * v.w;
        }
    }

    // Apply lane-constant corner sign, then reduce across lanes of same
    // parity (strides 2..16 preserve parity = channel half).
    if (neg) { acc.x = -acc.x; acc.y = -acc.y; acc.z = -acc.z; acc.w = -acc.w; }
    #pragma unroll
    for (int d = 2; d <= 16; d <<= 1) {
        acc.x += __shfl_xor_sync(0xffffffffu, acc.x, d);
        acc.y += __shfl_xor_sync(0xffffffffu, acc.y, d);
        acc.z += __shfl_xor_sync(0xffffffffu, acc.z, d);
        acc.w += __shfl_xor_sync(0xffffffffu, acc.w, d);
    }

    if (l < 2) {
        const float s = 1.f / 49.f;
        ((float4*)(out + (size_t)warp * 8))[l] =
            make_float4(acc.x * s, acc.y * s, acc.z * s, acc.w * s);
    }
}

// ---------------------------------------------------------------------------
extern "C" void kernel_launch(void* const* d_in, const int* in_sizes, int n_in,
                              void* d_out, int out_size) {
    const float* conv = (const float*)d_in[0];   // [8,1024,1024] fp32
    const int*   rois = (const int*)d_in[1];     // [n,4] int32
    float*       out  = (float*)d_out;           // [n,8] fp32
    const int n = in_sizes[1] / 4;

    rowscan_kernel<<<HH, 256>>>(conv);
    colscan_kernel<<<NSEG * (NCOL / 256), 256>>>();
    pool_kernel   <<<(n + 7) / 8, 256>>>(rois, out, n);
}